// round 8
// baseline (speedup 1.0000x reference)
#include <cuda_runtime.h>
#include <math.h>

#define NN      4096
#define INDIM   256
#define ODIM    256
#define HEADS   4
#define HDIM    64
#define SPLITS  8
#define JCHUNK  (NN / SPLITS)     // 512
#define JT      16                // j-tile rows
#define NT      (JCHUNK / JT)     // 32 tiles
#define PITCH   36                // psm pitch (floats): 16B-aligned rows

// -------- scratch (no allocations allowed) --------
__device__ float  g_hcat [NN * ODIM];          // h concat: [n][h*64+k]
__device__ float  g_resid[NN * ODIM];          // x@Wr + br
__device__ float  g_scol [HEADS * NN];         // a1 . h
__device__ float  g_srow [HEADS * NN];         // a2 . h
__device__ float4 g_sB   [HEADS * NN];         // (s_col, exp(s_col), exp(0.2 s_col), 0)
__device__ float  g_gmax [HEADS];              // per-head global max of s_col
__device__ float  g_pacc [SPLITS * NN * ODIM]; // partial PV numerators
__device__ float  g_pden [SPLITS * HEADS * NN];// partial softmax denominators

// ============================================================
// Kernel 1: fused GEMM  out[4096][512]
//   cols 0..255   -> g_hcat  (x @ Wcat)
//   cols 256..511 -> g_resid (x @ Wr + br)
// ============================================================
__global__ __launch_bounds__(256) void k_gemm(
    const float* __restrict__ x, const float* __restrict__ W,
    const float* __restrict__ Wr, const float* __restrict__ br)
{
    __shared__ float As[16][68];
    __shared__ float Bs[16][68];
    const int tid = threadIdx.x;
    const int tx = tid & 15, ty = tid >> 4;
    const int m0 = blockIdx.y * 64;
    const int n0 = blockIdx.x * 64;

    float acc[4][4];
    #pragma unroll
    for (int i = 0; i < 4; i++)
        #pragma unroll
        for (int j = 0; j < 4; j++) acc[i][j] = 0.f;

    for (int k0 = 0; k0 < INDIM; k0 += 16) {
        #pragma unroll
        for (int q = 0; q < 4; q++) {
            int idx = tid + q * 256;
            int r = idx >> 4, kk = idx & 15;
            As[kk][r] = x[(m0 + r) * INDIM + k0 + kk];
        }
        #pragma unroll
        for (int q = 0; q < 4; q++) {
            int idx = tid + q * 256;
            int kk = idx >> 6, c = idx & 63;
            int cg = n0 + c;
            float v;
            if (cg < ODIM)
                v = W[(cg >> 6) * (INDIM * HDIM) + (k0 + kk) * HDIM + (cg & 63)];
            else
                v = Wr[(k0 + kk) * ODIM + (cg - ODIM)];
            Bs[kk][c] = v;
        }
        __syncthreads();
        #pragma unroll
        for (int kk = 0; kk < 16; kk++) {
            float a[4], b[4];
            #pragma unroll
            for (int i = 0; i < 4; i++) a[i] = As[kk][ty * 4 + i];
            #pragma unroll
            for (int j = 0; j < 4; j++) b[j] = Bs[kk][tx * 4 + j];
            #pragma unroll
            for (int i = 0; i < 4; i++)
                #pragma unroll
                for (int j = 0; j < 4; j++) acc[i][j] += a[i] * b[j];
        }
        __syncthreads();
    }
    #pragma unroll
    for (int i = 0; i < 4; i++) {
        int rg = m0 + ty * 4 + i;
        #pragma unroll
        for (int j = 0; j < 4; j++) {
            int cg = n0 + tx * 4 + j;
            if (cg < ODIM) g_hcat[rg * ODIM + cg] = acc[i][j];
            else           g_resid[rg * ODIM + (cg - ODIM)] = acc[i][j] + br[cg - ODIM];
        }
    }
}

// ============================================================
// Kernel 2: s_col / s_row + packed (s, B1, B2) float4
// ============================================================
__global__ __launch_bounds__(256) void k_scores(
    const float* __restrict__ a1, const float* __restrict__ a2)
{
    __shared__ float hs[32 * 256];
    const int tid = threadIdx.x;
    const int i0 = blockIdx.x * 32;
    #pragma unroll
    for (int q = 0; q < 32; q++)
        hs[tid + q * 256] = g_hcat[i0 * ODIM + tid + q * 256];
    __syncthreads();
    if (tid < 128) {
        int r = tid >> 2, h = tid & 3;
        int lane = tid & 31;
        float s1 = 0.f, s2 = 0.f;
        #pragma unroll
        for (int k0 = 0; k0 < HDIM; k0++) {
            int k = (k0 + lane) & 63;
            float hv = hs[r * 256 + h * 64 + k];
            s1 += hv * a1[h * 64 + k];
            s2 += hv * a2[h * 64 + k];
        }
        g_scol[h * NN + i0 + r] = s1;
        g_srow[h * NN + i0 + r] = s2;
        g_sB  [h * NN + i0 + r] = make_float4(s1, __expf(s1), __expf(0.2f * s1), 0.f);
    }
}

// ============================================================
// Kernel 2b: per-head global max of s_col
// ============================================================
__global__ __launch_bounds__(256) void k_gmax()
{
    __shared__ float red[256];
    const int tid = threadIdx.x;
    const int h = tid >> 6, l = tid & 63;
    float m = -1e30f;
    for (int n = l; n < NN; n += 64)
        m = fmaxf(m, g_scol[h * NN + n]);
    red[tid] = m;
    __syncthreads();
    for (int s = 32; s >= 1; s >>= 1) {
        if (l < s) red[tid] = fmaxf(red[tid], red[tid + s]);
        __syncthreads();
    }
    if (l == 0) g_gmax[h] = red[tid];
}

// ============================================================
// Kernel 3: software-pipelined split-j attention + PV partials.
//   p = adj ? ((si+sj>0) ? A1_i*B1_j : A2_i*B2_j) : 0   (no exp in loop)
// Prefetch next tile (h as float4 regs, adj folded into a bitmask, sB as
// one float4) right after the produce-barrier -> hidden under consumer.
// ============================================================
__global__ __launch_bounds__(256, 2) void k_attn(
    const int* __restrict__ adj)
{
    __shared__ __align__(16) float hsm[JT * 256];            // 16 KB
    __shared__ __align__(16) float psm[HEADS * JT * PITCH];  // 9.2 KB

    const int tid  = threadIdx.x;
    const int i0   = blockIdx.x * 32;
    const int sOff = blockIdx.y * JCHUNK;

    // ---- producer mapping ----
    const int jj_p  = tid & 15;
    const int hh    = (tid >> 4) & 3;
    const int rbase = (tid >> 6) * 8;

    // ---- consumer mapping ----
    const int cg = tid & 127;
    const int c0 = 2 * cg;
    const int r0 = (tid >> 7) * 16;
    const int hd = cg >> 5;

    float si8[8], A1r[8], A2r[8], den8[8];
    {
        float gm = g_gmax[hh];
        #pragma unroll
        for (int k = 0; k < 8; k++) {
            float s = g_srow[hh * NN + i0 + rbase + k];
            si8[k] = s;
            float mm = s + gm;
            mm = mm > 0.f ? mm : 0.2f * mm;            // safe row max
            A1r[k] = __expf(s - mm);
            A2r[k] = __expf(0.2f * s - mm);
            den8[k] = 0.f;
        }
    }

    float2 acc[16];
    #pragma unroll
    for (int k = 0; k < 16; k++) acc[k] = make_float2(0.f, 0.f);

    // ---- prefetch tile 0 ----
    float4       hreg[4];
    unsigned int amask;
    float4       sreg;
    {
        const float4* src = (const float4*)(g_hcat + (size_t)sOff * ODIM);
        #pragma unroll
        for (int q = 0; q < 4; q++) hreg[q] = src[tid + q * 256];
        const int* arow = adj + (size_t)(i0 + rbase) * NN + sOff + jj_p;
        amask = 0u;
        #pragma unroll
        for (int k = 0; k < 8; k++)
            amask |= (arow[(size_t)k * NN] > 0) ? (1u << k) : 0u;
        sreg = g_sB[hh * NN + sOff + jj_p];
    }

    for (int t = 0; t < NT; t++) {
        // --- stage h tile from registers ---
        {
            float4* dst = (float4*)hsm;
            #pragma unroll
            for (int q = 0; q < 4; q++)
                dst[tid + q * 256] = hreg[q];
        }
        // --- produce p tile from registers ---
        {
            float p8[8];
            #pragma unroll
            for (int k = 0; k < 8; k++) {
                bool pos = (si8[k] + sreg.x) > 0.f;
                float p = (pos ? A1r[k] : A2r[k]) * (pos ? sreg.y : sreg.z);
                p = (amask & (1u << k)) ? p : 0.f;
                p8[k] = p;
                den8[k] += p;
            }
            float* pdst = psm + (hh * JT + jj_p) * PITCH + rbase;
            *(float4*)(pdst)     = make_float4(p8[0], p8[1], p8[2], p8[3]);
            *(float4*)(pdst + 4) = make_float4(p8[4], p8[5], p8[6], p8[7]);
        }
        __syncthreads();

        // --- prefetch next tile (hidden under consumer phase) ---
        if (t + 1 < NT) {
            const int j1 = sOff + (t + 1) * JT;
            const float4* src = (const float4*)(g_hcat + (size_t)j1 * ODIM);
            #pragma unroll
            for (int q = 0; q < 4; q++) hreg[q] = src[tid + q * 256];
            const int* arow = adj + (size_t)(i0 + rbase) * NN + j1 + jj_p;
            amask = 0u;
            #pragma unroll
            for (int k = 0; k < 8; k++)
                amask |= (arow[(size_t)k * NN] > 0) ? (1u << k) : 0u;
            sreg = g_sB[hh * NN + j1 + jj_p];
        }

        // --- PV accumulate ---
        #pragma unroll 4
        for (int jj = 0; jj < JT; jj++) {
            float2 hv = *(const float2*)(hsm + jj * 256 + c0);
            const float4* prow = (const float4*)(psm + (hd * JT + jj) * PITCH + r0);
            float4 p0 = prow[0], p1 = prow[1], p2 = prow[2], p3 = prow[3];
            acc[0].x  += p0.x * hv.x;  acc[0].y  += p0.x * hv.y;
            acc[1].x  += p0.y * hv.x;  acc[1].y  += p0.y * hv.y;
            acc[2].x  += p0.z * hv.x;  acc[2].y  += p0.z * hv.y;
            acc[3].x  += p0.w * hv.x;  acc[3].y  += p0.w * hv.y;
            acc[4].x  += p1.x * hv.x;  acc[4].y  += p1.x * hv.y;
            acc[5].x  += p1.y * hv.x;  acc[5].y  += p1.y * hv.y;
            acc[6].x  += p1.z * hv.x;  acc[6].y  += p1.z * hv.y;
            acc[7].x  += p1.w * hv.x;  acc[7].y  += p1.w * hv.y;
            acc[8].x  += p2.x * hv.x;  acc[8].y  += p2.x * hv.y;
            acc[9].x  += p2.y * hv.x;  acc[9].y  += p2.y * hv.y;
            acc[10].x += p2.z * hv.x;  acc[10].y += p2.z * hv.y;
            acc[11].x += p2.w * hv.x;  acc[11].y += p2.w * hv.y;
            acc[12].x += p3.x * hv.x;  acc[12].y += p3.x * hv.y;
            acc[13].x += p3.y * hv.x;  acc[13].y += p3.y * hv.y;
            acc[14].x += p3.z * hv.x;  acc[14].y += p3.z * hv.y;
            acc[15].x += p3.w * hv.x;  acc[15].y += p3.w * hv.y;
        }
        __syncthreads();
    }

    // --- write PV partials (float2, coalesced) ---
    {
        float* outp = g_pacc + ((size_t)blockIdx.y * NN + i0 + r0) * ODIM + c0;
        #pragma unroll
        for (int k = 0; k < 16; k++)
            *(float2*)(outp + (size_t)k * ODIM) = acc[k];
    }
    // --- reduce denominators across the 16 jj lanes ---
    #pragma unroll
    for (int k = 0; k < 8; k++) {
        #pragma unroll
        for (int m = 1; m < 16; m <<= 1)
            den8[k] += __shfl_xor_sync(0xFFFFFFFFu, den8[k], m);
    }
    if ((tid & 15) == 0) {
        #pragma unroll
        for (int k = 0; k < 8; k++)
            g_pden[((size_t)blockIdx.y * HEADS + hh) * NN + i0 + rbase + k] = den8[k];
    }
}

// ============================================================
// Kernel 4: reduce splits + softmax div + ELU + residual + LayerNorm
// ============================================================
__global__ __launch_bounds__(256) void k_final(
    const float* __restrict__ gamma, const float* __restrict__ beta,
    float* __restrict__ out)
{
    __shared__ float ysm[32 * 256];
    __shared__ float densm[32 * 4];
    const int tid = threadIdx.x;
    const int i0 = blockIdx.x * 32;
    const int c = tid;
    const int hd = c >> 6;

    if (tid < 128) {
        int hh = tid & 3, r = tid >> 2;
        float d = 0.f;
        #pragma unroll
        for (int s = 0; s < SPLITS; s++)
            d += g_pden[((size_t)s * HEADS + hh) * NN + i0 + r];
        densm[r * 4 + hh] = d;
    }
    __syncthreads();

    #pragma unroll 4
    for (int r = 0; r < 32; r++) {
        float a = 0.f;
        #pragma unroll
        for (int s = 0; s < SPLITS; s++)
            a += g_pacc[((size_t)s * NN + i0 + r) * ODIM + c];
        float v = a / densm[r * 4 + hd];
        v = v > 0.f ? v : (__expf(v) - 1.f);        // ELU
        v += g_resid[(size_t)(i0 + r) * ODIM + c];
        ysm[r * 256 + c] = v;
    }
    __syncthreads();

    const int w = tid >> 5, lane = tid & 31;
    #pragma unroll
    for (int rr = 0; rr < 4; rr++) {
        int r = w * 4 + rr;
        float s = 0.f, sq = 0.f;
        #pragma unroll
        for (int q = 0; q < 8; q++) {
            float v = ysm[r * 256 + lane + q * 32];
            s += v; sq += v * v;
        }
        #pragma unroll
        for (int o = 16; o > 0; o >>= 1) {
            s  += __shfl_xor_sync(0xFFFFFFFFu, s,  o);
            sq += __shfl_xor_sync(0xFFFFFFFFu, sq, o);
        }
        float mu   = s * (1.f / 256.f);
        float var  = sq * (1.f / 256.f) - mu * mu;
        float rstd = rsqrtf(var + 1e-5f);
        #pragma unroll
        for (int q = 0; q < 8; q++) {
            int cc = lane + q * 32;
            float v = ysm[r * 256 + cc];
            out[(size_t)(i0 + r) * ODIM + cc] = (v - mu) * rstd * gamma[cc] + beta[cc];
        }
    }
}

// ============================================================
extern "C" void kernel_launch(void* const* d_in, const int* in_sizes, int n_in,
                              void* d_out, int out_size)
{
    const float* x     = (const float*)d_in[0];
    const int*   adj   = (const int*)  d_in[1];
    const float* W     = (const float*)d_in[2];
    const float* a1    = (const float*)d_in[3];
    const float* a2    = (const float*)d_in[4];
    const float* Wr    = (const float*)d_in[5];
    const float* br    = (const float*)d_in[6];
    const float* gamma = (const float*)d_in[7];
    const float* beta  = (const float*)d_in[8];
    float* out = (float*)d_out;

    k_gemm  <<<dim3(512 / 64, NN / 64), 256>>>(x, W, Wr, br);
    k_scores<<<NN / 32, 256>>>(a1, a2);
    k_gmax  <<<1, 256>>>();
    k_attn  <<<dim3(NN / 32, SPLITS), 256>>>(adj);
    k_final <<<NN / 32, 256>>>(gamma, beta, out);
}

// round 9
// speedup vs baseline: 1.1113x; 1.1113x over previous
#include <cuda_runtime.h>
#include <cuda_pipeline.h>
#include <math.h>

#define NN      4096
#define INDIM   256
#define ODIM    256
#define HEADS   4
#define HDIM    64
#define SPLITS  7
#define JT      16                // j-tile rows
#define NTILES  (NN / JT)         // 256 total tiles
#define PITCH   36                // psm pitch (floats): 16B-aligned rows

// -------- scratch (no allocations allowed) --------
__device__ float  g_hcat [NN * ODIM];          // h concat: [n][h*64+k]
__device__ float  g_resid[NN * ODIM];          // x@Wr + br
__device__ float  g_scol [HEADS * NN];         // a1 . h
__device__ float  g_srow [HEADS * NN];         // a2 . h
__device__ float4 g_sB   [HEADS * NN];         // (s_col, exp(s_col), exp(0.2 s_col), 0)
__device__ float  g_gmax [HEADS];              // per-head global max of s_col
__device__ float  g_pacc [SPLITS * NN * ODIM]; // partial PV numerators
__device__ float  g_pden [SPLITS * HEADS * NN];// partial softmax denominators

// ============================================================
// Kernel 1: fused GEMM  out[4096][512]
// ============================================================
__global__ __launch_bounds__(256) void k_gemm(
    const float* __restrict__ x, const float* __restrict__ W,
    const float* __restrict__ Wr, const float* __restrict__ br)
{
    __shared__ float As[16][68];
    __shared__ float Bs[16][68];
    const int tid = threadIdx.x;
    const int tx = tid & 15, ty = tid >> 4;
    const int m0 = blockIdx.y * 64;
    const int n0 = blockIdx.x * 64;

    float acc[4][4];
    #pragma unroll
    for (int i = 0; i < 4; i++)
        #pragma unroll
        for (int j = 0; j < 4; j++) acc[i][j] = 0.f;

    for (int k0 = 0; k0 < INDIM; k0 += 16) {
        #pragma unroll
        for (int q = 0; q < 4; q++) {
            int idx = tid + q * 256;
            int r = idx >> 4, kk = idx & 15;
            As[kk][r] = x[(m0 + r) * INDIM + k0 + kk];
        }
        #pragma unroll
        for (int q = 0; q < 4; q++) {
            int idx = tid + q * 256;
            int kk = idx >> 6, c = idx & 63;
            int cg = n0 + c;
            float v;
            if (cg < ODIM)
                v = W[(cg >> 6) * (INDIM * HDIM) + (k0 + kk) * HDIM + (cg & 63)];
            else
                v = Wr[(k0 + kk) * ODIM + (cg - ODIM)];
            Bs[kk][c] = v;
        }
        __syncthreads();
        #pragma unroll
        for (int kk = 0; kk < 16; kk++) {
            float a[4], b[4];
            #pragma unroll
            for (int i = 0; i < 4; i++) a[i] = As[kk][ty * 4 + i];
            #pragma unroll
            for (int j = 0; j < 4; j++) b[j] = Bs[kk][tx * 4 + j];
            #pragma unroll
            for (int i = 0; i < 4; i++)
                #pragma unroll
                for (int j = 0; j < 4; j++) acc[i][j] += a[i] * b[j];
        }
        __syncthreads();
    }
    #pragma unroll
    for (int i = 0; i < 4; i++) {
        int rg = m0 + ty * 4 + i;
        #pragma unroll
        for (int j = 0; j < 4; j++) {
            int cg = n0 + tx * 4 + j;
            if (cg < ODIM) g_hcat[rg * ODIM + cg] = acc[i][j];
            else           g_resid[rg * ODIM + (cg - ODIM)] = acc[i][j] + br[cg - ODIM];
        }
    }
}

// ============================================================
// Kernel 2: s_col / s_row + packed (s, B1, B2) float4
// ============================================================
__global__ __launch_bounds__(256) void k_scores(
    const float* __restrict__ a1, const float* __restrict__ a2)
{
    __shared__ float hs[32 * 256];
    const int tid = threadIdx.x;
    const int i0 = blockIdx.x * 32;
    #pragma unroll
    for (int q = 0; q < 32; q++)
        hs[tid + q * 256] = g_hcat[i0 * ODIM + tid + q * 256];
    __syncthreads();
    if (tid < 128) {
        int r = tid >> 2, h = tid & 3;
        int lane = tid & 31;
        float s1 = 0.f, s2 = 0.f;
        #pragma unroll
        for (int k0 = 0; k0 < HDIM; k0++) {
            int k = (k0 + lane) & 63;
            float hv = hs[r * 256 + h * 64 + k];
            s1 += hv * a1[h * 64 + k];
            s2 += hv * a2[h * 64 + k];
        }
        g_scol[h * NN + i0 + r] = s1;
        g_srow[h * NN + i0 + r] = s2;
        g_sB  [h * NN + i0 + r] = make_float4(s1, __expf(s1), __expf(0.2f * s1), 0.f);
    }
}

// ============================================================
// Kernel 2b: per-head global max of s_col
// ============================================================
__global__ __launch_bounds__(256) void k_gmax()
{
    __shared__ float red[256];
    const int tid = threadIdx.x;
    const int h = tid >> 6, l = tid & 63;
    float m = -1e30f;
    for (int n = l; n < NN; n += 64)
        m = fmaxf(m, g_scol[h * NN + n]);
    red[tid] = m;
    __syncthreads();
    for (int s = 32; s >= 1; s >>= 1) {
        if (l < s) red[tid] = fmaxf(red[tid], red[tid + s]);
        __syncthreads();
    }
    if (l == 0) g_gmax[h] = red[tid];
}

// ============================================================
// Kernel 3: split-j attention + PV partials, cp.async double-buffered.
//   p = adj ? ((si+sj>0) ? A1_i*B1_j : A2_i*B2_j) : 0   (no exp in loop)
// Per tile: produce p from smem-prefetched adj/sB; barrier; issue cp.async
// prefetch of (h, adj, sB) for t+1 into buf^1; consume; wait; barrier.
// Splits 0-3 get 37 tiles, 4-6 get 36 (grid 896 ~ 3.03 waves).
// ============================================================
__global__ __launch_bounds__(256, 2) void k_attn(
    const int* __restrict__ adj)
{
    __shared__ __align__(16) float  hsm[2][JT * 256];         // 32 KB
    __shared__ __align__(16) float  psm[HEADS * JT * PITCH];  // 9.2 KB
    __shared__ __align__(16) int    adjsm[2][32 * JT];        // 4 KB
    __shared__ __align__(16) float4 sbsm[2][HEADS * JT];      // 2 KB

    const int tid = threadIdx.x;
    const int i0  = blockIdx.x * 32;
    const int sp  = blockIdx.y;
    const int tb  = sp * 36 + (sp < 4 ? sp : 4);   // first tile index
    const int tn  = 36 + (sp < 4 ? 1 : 0);         // tile count

    // ---- producer mapping ----
    const int jj_p  = tid & 15;
    const int hh    = (tid >> 4) & 3;
    const int rbase = (tid >> 6) * 8;

    // ---- consumer mapping ----
    const int cg = tid & 127;
    const int c0 = 2 * cg;
    const int r0 = (tid >> 7) * 16;
    const int hd = cg >> 5;

    // ---- prefetch mapping ----
    const int pf_jj = tid & 15;
    const int pf_r  = tid >> 4;                    // 0..15

    float si8[8], A1r[8], A2r[8], den8[8];
    {
        float gm = g_gmax[hh];
        #pragma unroll
        for (int k = 0; k < 8; k++) {
            float s = g_srow[hh * NN + i0 + rbase + k];
            si8[k] = s;
            float mm = s + gm;
            mm = mm > 0.f ? mm : 0.2f * mm;        // safe row max
            A1r[k] = __expf(s - mm);
            A2r[k] = __expf(0.2f * s - mm);
            den8[k] = 0.f;
        }
    }

    float2 acc[16];
    #pragma unroll
    for (int k = 0; k < 16; k++) acc[k] = make_float2(0.f, 0.f);

    // ---- prefetch tile 0 into buffer 0 ----
    {
        const int j0 = tb * JT;
        const float4* hs = (const float4*)(g_hcat + (size_t)j0 * ODIM);
        #pragma unroll
        for (int q = 0; q < 4; q++)
            __pipeline_memcpy_async(&((float4*)hsm[0])[tid + q * 256],
                                    &hs[tid + q * 256], 16);
        __pipeline_memcpy_async(&adjsm[0][pf_r * JT + pf_jj],
                                &adj[(size_t)(i0 + pf_r) * NN + j0 + pf_jj], 4);
        __pipeline_memcpy_async(&adjsm[0][(pf_r + 16) * JT + pf_jj],
                                &adj[(size_t)(i0 + pf_r + 16) * NN + j0 + pf_jj], 4);
        if (tid < 64)
            __pipeline_memcpy_async(&sbsm[0][(tid >> 4) * JT + (tid & 15)],
                                    &g_sB[(tid >> 4) * NN + j0 + (tid & 15)], 16);
        __pipeline_commit();
        __pipeline_wait_prior(0);
    }
    __syncthreads();

    for (int t = 0; t < tn; t++) {
        const int buf = t & 1;

        // --- produce p tile from smem-resident adj/sB ---
        {
            float4 sreg = sbsm[buf][hh * JT + jj_p];
            float p8[8];
            #pragma unroll
            for (int k = 0; k < 8; k++) {
                int av = adjsm[buf][(rbase + k) * JT + jj_p];
                bool pos = (si8[k] + sreg.x) > 0.f;
                float p = (pos ? A1r[k] : A2r[k]) * (pos ? sreg.y : sreg.z);
                p = (av > 0) ? p : 0.f;
                p8[k] = p;
                den8[k] += p;
            }
            float* pdst = psm + (hh * JT + jj_p) * PITCH + rbase;
            *(float4*)(pdst)     = make_float4(p8[0], p8[1], p8[2], p8[3]);
            *(float4*)(pdst + 4) = make_float4(p8[4], p8[5], p8[6], p8[7]);
        }
        __syncthreads();

        // --- issue cp.async prefetch for t+1 (register-free) ---
        const bool more = (t + 1 < tn);
        if (more) {
            const int j1 = (tb + t + 1) * JT;
            const int nb = buf ^ 1;
            const float4* hs = (const float4*)(g_hcat + (size_t)j1 * ODIM);
            #pragma unroll
            for (int q = 0; q < 4; q++)
                __pipeline_memcpy_async(&((float4*)hsm[nb])[tid + q * 256],
                                        &hs[tid + q * 256], 16);
            __pipeline_memcpy_async(&adjsm[nb][pf_r * JT + pf_jj],
                                    &adj[(size_t)(i0 + pf_r) * NN + j1 + pf_jj], 4);
            __pipeline_memcpy_async(&adjsm[nb][(pf_r + 16) * JT + pf_jj],
                                    &adj[(size_t)(i0 + pf_r + 16) * NN + j1 + pf_jj], 4);
            if (tid < 64)
                __pipeline_memcpy_async(&sbsm[nb][(tid >> 4) * JT + (tid & 15)],
                                        &g_sB[(tid >> 4) * NN + j1 + (tid & 15)], 16);
            __pipeline_commit();
        }

        // --- PV accumulate ---
        #pragma unroll 4
        for (int jj = 0; jj < JT; jj++) {
            float2 hv = *(const float2*)(&hsm[buf][jj * 256 + c0]);
            const float4* prow = (const float4*)(psm + (hd * JT + jj) * PITCH + r0);
            float4 p0 = prow[0], p1 = prow[1], p2 = prow[2], p3 = prow[3];
            acc[0].x  += p0.x * hv.x;  acc[0].y  += p0.x * hv.y;
            acc[1].x  += p0.y * hv.x;  acc[1].y  += p0.y * hv.y;
            acc[2].x  += p0.z * hv.x;  acc[2].y  += p0.z * hv.y;
            acc[3].x  += p0.w * hv.x;  acc[3].y  += p0.w * hv.y;
            acc[4].x  += p1.x * hv.x;  acc[4].y  += p1.x * hv.y;
            acc[5].x  += p1.y * hv.x;  acc[5].y  += p1.y * hv.y;
            acc[6].x  += p1.z * hv.x;  acc[6].y  += p1.z * hv.y;
            acc[7].x  += p1.w * hv.x;  acc[7].y  += p1.w * hv.y;
            acc[8].x  += p2.x * hv.x;  acc[8].y  += p2.x * hv.y;
            acc[9].x  += p2.y * hv.x;  acc[9].y  += p2.y * hv.y;
            acc[10].x += p2.z * hv.x;  acc[10].y += p2.z * hv.y;
            acc[11].x += p2.w * hv.x;  acc[11].y += p2.w * hv.y;
            acc[12].x += p3.x * hv.x;  acc[12].y += p3.x * hv.y;
            acc[13].x += p3.y * hv.x;  acc[13].y += p3.y * hv.y;
            acc[14].x += p3.z * hv.x;  acc[14].y += p3.z * hv.y;
            acc[15].x += p3.w * hv.x;  acc[15].y += p3.w * hv.y;
        }

        if (more) __pipeline_wait_prior(0);
        __syncthreads();
    }

    // --- write PV partials (float2, coalesced) ---
    {
        float* outp = g_pacc + ((size_t)sp * NN + i0 + r0) * ODIM + c0;
        #pragma unroll
        for (int k = 0; k < 16; k++)
            *(float2*)(outp + (size_t)k * ODIM) = acc[k];
    }
    // --- reduce denominators across the 16 jj lanes ---
    #pragma unroll
    for (int k = 0; k < 8; k++) {
        #pragma unroll
        for (int m = 1; m < 16; m <<= 1)
            den8[k] += __shfl_xor_sync(0xFFFFFFFFu, den8[k], m);
    }
    if ((tid & 15) == 0) {
        #pragma unroll
        for (int k = 0; k < 8; k++)
            g_pden[((size_t)sp * HEADS + hh) * NN + i0 + rbase + k] = den8[k];
    }
}

// ============================================================
// Kernel 4: reduce splits + softmax div + ELU + residual + LayerNorm
// ============================================================
__global__ __launch_bounds__(256) void k_final(
    const float* __restrict__ gamma, const float* __restrict__ beta,
    float* __restrict__ out)
{
    __shared__ float ysm[32 * 256];
    __shared__ float densm[32 * 4];
    const int tid = threadIdx.x;
    const int i0 = blockIdx.x * 32;
    const int c = tid;
    const int hd = c >> 6;

    if (tid < 128) {
        int hh = tid & 3, r = tid >> 2;
        float d = 0.f;
        #pragma unroll
        for (int s = 0; s < SPLITS; s++)
            d += g_pden[((size_t)s * HEADS + hh) * NN + i0 + r];
        densm[r * 4 + hh] = d;
    }
    __syncthreads();

    #pragma unroll 4
    for (int r = 0; r < 32; r++) {
        float a = 0.f;
        #pragma unroll
        for (int s = 0; s < SPLITS; s++)
            a += g_pacc[((size_t)s * NN + i0 + r) * ODIM + c];
        float v = a / densm[r * 4 + hd];
        v = v > 0.f ? v : (__expf(v) - 1.f);        // ELU
        v += g_resid[(size_t)(i0 + r) * ODIM + c];
        ysm[r * 256 + c] = v;
    }
    __syncthreads();

    const int w = tid >> 5, lane = tid & 31;
    #pragma unroll
    for (int rr = 0; rr < 4; rr++) {
        int r = w * 4 + rr;
        float s = 0.f, sq = 0.f;
        #pragma unroll
        for (int q = 0; q < 8; q++) {
            float v = ysm[r * 256 + lane + q * 32];
            s += v; sq += v * v;
        }
        #pragma unroll
        for (int o = 16; o > 0; o >>= 1) {
            s  += __shfl_xor_sync(0xFFFFFFFFu, s,  o);
            sq += __shfl_xor_sync(0xFFFFFFFFu, sq, o);
        }
        float mu   = s * (1.f / 256.f);
        float var  = sq * (1.f / 256.f) - mu * mu;
        float rstd = rsqrtf(var + 1e-5f);
        #pragma unroll
        for (int q = 0; q < 8; q++) {
            int cc = lane + q * 32;
            float v = ysm[r * 256 + cc];
            out[(size_t)(i0 + r) * ODIM + cc] = (v - mu) * rstd * gamma[cc] + beta[cc];
        }
    }
}

// ============================================================
extern "C" void kernel_launch(void* const* d_in, const int* in_sizes, int n_in,
                              void* d_out, int out_size)
{
    const float* x     = (const float*)d_in[0];
    const int*   adj   = (const int*)  d_in[1];
    const float* W     = (const float*)d_in[2];
    const float* a1    = (const float*)d_in[3];
    const float* a2    = (const float*)d_in[4];
    const float* Wr    = (const float*)d_in[5];
    const float* br    = (const float*)d_in[6];
    const float* gamma = (const float*)d_in[7];
    const float* beta  = (const float*)d_in[8];
    float* out = (float*)d_out;

    k_gemm  <<<dim3(512 / 64, NN / 64), 256>>>(x, W, Wr, br);
    k_scores<<<NN / 32, 256>>>(a1, a2);
    k_gmax  <<<1, 256>>>();
    k_attn  <<<dim3(NN / 32, SPLITS), 256>>>(adj);
    k_final <<<NN / 32, 256>>>(gamma, beta, out);
}

// round 11
// speedup vs baseline: 1.1705x; 1.0532x over previous
#include <cuda_runtime.h>
#include <cuda_pipeline.h>
#include <math.h>

#define NN      4096
#define INDIM   256
#define ODIM    256
#define HEADS   4
#define HDIM    64
#define SPLITS  7
#define JT      16                // j-tile rows
#define PITCH   36                // psm pitch (floats): 16B-aligned rows

// -------- scratch (no allocations allowed) --------
__device__ float  g_hcat [NN * ODIM];          // h concat: [n][h*64+k]
__device__ float  g_resid[NN * ODIM];          // x@Wr + br
__device__ float  g_scol [HEADS * NN];         // a1 . h
__device__ float  g_srow [HEADS * NN];         // a2 . h
__device__ float4 g_sB   [HEADS * NN];         // (s_col, exp(s_col), exp(0.2 s_col), 0)
__device__ float  g_gmax [HEADS];              // per-head global max of s_col
__device__ float  g_pacc [SPLITS * NN * ODIM]; // partial PV numerators
__device__ float  g_pden [SPLITS * HEADS * NN];// partial softmax denominators

// ---- packed fp32x2 helpers (Blackwell sm_100+) ----
__device__ __forceinline__ unsigned long long pack2(float a, float b)
{
    unsigned long long r;
    asm("mov.b64 %0, {%1, %2};" : "=l"(r) : "f"(a), "f"(b));
    return r;
}
__device__ __forceinline__ void unpack2(unsigned long long v, float& a, float& b)
{
    asm("mov.b64 {%0, %1}, %2;" : "=f"(a), "=f"(b) : "l"(v));
}
__device__ __forceinline__ void ffma2(unsigned long long& acc,
                                      unsigned long long a,
                                      unsigned long long b)
{
    asm("fma.rn.f32x2 %0, %1, %2, %0;" : "+l"(acc) : "l"(a), "l"(b));
}

// ============================================================
// Kernel 1: fused GEMM  out[4096][512]
// ============================================================
__global__ __launch_bounds__(256) void k_gemm(
    const float* __restrict__ x, const float* __restrict__ W,
    const float* __restrict__ Wr, const float* __restrict__ br)
{
    __shared__ float As[16][68];
    __shared__ float Bs[16][68];
    const int tid = threadIdx.x;
    const int tx = tid & 15, ty = tid >> 4;
    const int m0 = blockIdx.y * 64;
    const int n0 = blockIdx.x * 64;

    float acc[4][4];
    #pragma unroll
    for (int i = 0; i < 4; i++)
        #pragma unroll
        for (int j = 0; j < 4; j++) acc[i][j] = 0.f;

    for (int k0 = 0; k0 < INDIM; k0 += 16) {
        #pragma unroll
        for (int q = 0; q < 4; q++) {
            int idx = tid + q * 256;
            int r = idx >> 4, kk = idx & 15;
            As[kk][r] = x[(m0 + r) * INDIM + k0 + kk];
        }
        #pragma unroll
        for (int q = 0; q < 4; q++) {
            int idx = tid + q * 256;
            int kk = idx >> 6, c = idx & 63;
            int cg = n0 + c;
            float v;
            if (cg < ODIM)
                v = W[(cg >> 6) * (INDIM * HDIM) + (k0 + kk) * HDIM + (cg & 63)];
            else
                v = Wr[(k0 + kk) * ODIM + (cg - ODIM)];
            Bs[kk][c] = v;
        }
        __syncthreads();
        #pragma unroll
        for (int kk = 0; kk < 16; kk++) {
            float a[4], b[4];
            #pragma unroll
            for (int i = 0; i < 4; i++) a[i] = As[kk][ty * 4 + i];
            #pragma unroll
            for (int j = 0; j < 4; j++) b[j] = Bs[kk][tx * 4 + j];
            #pragma unroll
            for (int i = 0; i < 4; i++)
                #pragma unroll
                for (int j = 0; j < 4; j++) acc[i][j] += a[i] * b[j];
        }
        __syncthreads();
    }
    #pragma unroll
    for (int i = 0; i < 4; i++) {
        int rg = m0 + ty * 4 + i;
        #pragma unroll
        for (int j = 0; j < 4; j++) {
            int cg = n0 + tx * 4 + j;
            if (cg < ODIM) g_hcat[rg * ODIM + cg] = acc[i][j];
            else           g_resid[rg * ODIM + (cg - ODIM)] = acc[i][j] + br[cg - ODIM];
        }
    }
}

// ============================================================
// Kernel 2: s_col / s_row + packed (s, B1, B2) float4
// ============================================================
__global__ __launch_bounds__(256) void k_scores(
    const float* __restrict__ a1, const float* __restrict__ a2)
{
    __shared__ float hs[32 * 256];
    const int tid = threadIdx.x;
    const int i0 = blockIdx.x * 32;
    #pragma unroll
    for (int q = 0; q < 32; q++)
        hs[tid + q * 256] = g_hcat[i0 * ODIM + tid + q * 256];
    __syncthreads();
    if (tid < 128) {
        int r = tid >> 2, h = tid & 3;
        int lane = tid & 31;
        float s1 = 0.f, s2 = 0.f;
        #pragma unroll
        for (int k0 = 0; k0 < HDIM; k0++) {
            int k = (k0 + lane) & 63;
            float hv = hs[r * 256 + h * 64 + k];
            s1 += hv * a1[h * 64 + k];
            s2 += hv * a2[h * 64 + k];
        }
        g_scol[h * NN + i0 + r] = s1;
        g_srow[h * NN + i0 + r] = s2;
        g_sB  [h * NN + i0 + r] = make_float4(s1, __expf(s1), __expf(0.2f * s1), 0.f);
    }
}

// ============================================================
// Kernel 2b: per-head global max of s_col
// ============================================================
__global__ __launch_bounds__(256) void k_gmax()
{
    __shared__ float red[256];
    const int tid = threadIdx.x;
    const int h = tid >> 6, l = tid & 63;
    float m = -1e30f;
    for (int n = l; n < NN; n += 64)
        m = fmaxf(m, g_scol[h * NN + n]);
    red[tid] = m;
    __syncthreads();
    for (int s = 32; s >= 1; s >>= 1) {
        if (l < s) red[tid] = fmaxf(red[tid], red[tid + s]);
        __syncthreads();
    }
    if (l == 0) g_gmax[h] = red[tid];
}

// ============================================================
// Kernel 3: split-j attention + PV partials, cp.async double-buffered,
// packed f32x2 accumulation (row-pairs).
//   p = adj ? ((si+sj>0) ? A1_i*B1_j : A2_i*B2_j) : 0   (no exp in loop)
// ============================================================
__global__ __launch_bounds__(256, 2) void k_attn(
    const int* __restrict__ adj)
{
    __shared__ __align__(16) float  hsm[2][JT * 256];         // 32 KB
    __shared__ __align__(16) float  psm[HEADS * JT * PITCH];  // 9.2 KB
    __shared__ __align__(16) int    adjsm[2][32 * JT];        // 4 KB
    __shared__ __align__(16) float4 sbsm[2][HEADS * JT];      // 2 KB

    const int tid = threadIdx.x;
    const int i0  = blockIdx.x * 32;
    const int sp  = blockIdx.y;
    const int tb  = sp * 36 + (sp < 4 ? sp : 4);   // first tile index
    const int tn  = 36 + (sp < 4 ? 1 : 0);         // tile count

    // ---- producer mapping ----
    const int jj_p  = tid & 15;
    const int hh    = (tid >> 4) & 3;
    const int rbase = (tid >> 6) * 8;

    // ---- consumer mapping ----
    const int cg = tid & 127;
    const int c0 = 2 * cg;
    const int r0 = (tid >> 7) * 16;
    const int hd = cg >> 5;

    // ---- prefetch mapping ----
    const int pf_jj = tid & 15;
    const int pf_r  = tid >> 4;                    // 0..15

    float si8[8], A1r[8], A2r[8], den8[8];
    {
        float gm = g_gmax[hh];
        #pragma unroll
        for (int k = 0; k < 8; k++) {
            float s = g_srow[hh * NN + i0 + rbase + k];
            si8[k] = s;
            float mm = s + gm;
            mm = mm > 0.f ? mm : 0.2f * mm;        // safe row max
            A1r[k] = __expf(s - mm);
            A2r[k] = __expf(0.2f * s - mm);
            den8[k] = 0.f;
        }
    }

    // packed accumulators: accx[q] = rows (r0+2q, r0+2q+1) col c0
    //                      accy[q] = rows (r0+2q, r0+2q+1) col c0+1
    unsigned long long accx[8], accy[8];
    #pragma unroll
    for (int k = 0; k < 8; k++) { accx[k] = pack2(0.f, 0.f); accy[k] = pack2(0.f, 0.f); }

    // ---- prefetch tile 0 into buffer 0 ----
    {
        const int j0 = tb * JT;
        const float4* hs = (const float4*)(g_hcat + (size_t)j0 * ODIM);
        #pragma unroll
        for (int q = 0; q < 4; q++)
            __pipeline_memcpy_async(&((float4*)hsm[0])[tid + q * 256],
                                    &hs[tid + q * 256], 16);
        __pipeline_memcpy_async(&adjsm[0][pf_r * JT + pf_jj],
                                &adj[(size_t)(i0 + pf_r) * NN + j0 + pf_jj], 4);
        __pipeline_memcpy_async(&adjsm[0][(pf_r + 16) * JT + pf_jj],
                                &adj[(size_t)(i0 + pf_r + 16) * NN + j0 + pf_jj], 4);
        if (tid < 64)
            __pipeline_memcpy_async(&sbsm[0][(tid >> 4) * JT + (tid & 15)],
                                    &g_sB[(tid >> 4) * NN + j0 + (tid & 15)], 16);
        __pipeline_commit();
        __pipeline_wait_prior(0);
    }
    __syncthreads();

    for (int t = 0; t < tn; t++) {
        const int buf = t & 1;

        // --- produce p tile from smem-resident adj/sB ---
        {
            float4 sreg = sbsm[buf][hh * JT + jj_p];
            float p8[8];
            #pragma unroll
            for (int k = 0; k < 8; k++) {
                int av = adjsm[buf][(rbase + k) * JT + jj_p];
                bool pos = (si8[k] + sreg.x) > 0.f;
                float p = (pos ? A1r[k] : A2r[k]) * (pos ? sreg.y : sreg.z);
                p = (av > 0) ? p : 0.f;
                p8[k] = p;
                den8[k] += p;
            }
            float* pdst = psm + (hh * JT + jj_p) * PITCH + rbase;
            *(float4*)(pdst)     = make_float4(p8[0], p8[1], p8[2], p8[3]);
            *(float4*)(pdst + 4) = make_float4(p8[4], p8[5], p8[6], p8[7]);
        }
        __syncthreads();

        // --- issue cp.async prefetch for t+1 (register-free) ---
        const bool more = (t + 1 < tn);
        if (more) {
            const int j1 = (tb + t + 1) * JT;
            const int nb = buf ^ 1;
            const float4* hs = (const float4*)(g_hcat + (size_t)j1 * ODIM);
            #pragma unroll
            for (int q = 0; q < 4; q++)
                __pipeline_memcpy_async(&((float4*)hsm[nb])[tid + q * 256],
                                        &hs[tid + q * 256], 16);
            __pipeline_memcpy_async(&adjsm[nb][pf_r * JT + pf_jj],
                                    &adj[(size_t)(i0 + pf_r) * NN + j1 + pf_jj], 4);
            __pipeline_memcpy_async(&adjsm[nb][(pf_r + 16) * JT + pf_jj],
                                    &adj[(size_t)(i0 + pf_r + 16) * NN + j1 + pf_jj], 4);
            if (tid < 64)
                __pipeline_memcpy_async(&sbsm[nb][(tid >> 4) * JT + (tid & 15)],
                                        &g_sB[(tid >> 4) * NN + j1 + (tid & 15)], 16);
            __pipeline_commit();
        }

        // --- PV accumulate: packed f32x2 over row-pairs ---
        #pragma unroll 4
        for (int jj = 0; jj < JT; jj++) {
            float2 hv = *(const float2*)(&hsm[buf][jj * 256 + c0]);
            unsigned long long hx = pack2(hv.x, hv.x);
            unsigned long long hy = pack2(hv.y, hv.y);
            const ulonglong2* prow =
                (const ulonglong2*)(psm + (hd * JT + jj) * PITCH + r0);
            #pragma unroll
            for (int u = 0; u < 4; u++) {
                ulonglong2 pv = prow[u];   // pv.x = (p[4u],p[4u+1]), pv.y = (p[4u+2],p[4u+3])
                ffma2(accx[2 * u],     pv.x, hx);
                ffma2(accx[2 * u + 1], pv.y, hx);
                ffma2(accy[2 * u],     pv.x, hy);
                ffma2(accy[2 * u + 1], pv.y, hy);
            }
        }

        if (more) __pipeline_wait_prior(0);
        __syncthreads();
    }

    // --- write PV partials (float2 per row, coalesced) ---
    {
        float* outp = g_pacc + ((size_t)sp * NN + i0 + r0) * ODIM + c0;
        #pragma unroll
        for (int q = 0; q < 8; q++) {
            float ax0, ax1, ay0, ay1;
            unpack2(accx[q], ax0, ax1);
            unpack2(accy[q], ay0, ay1);
            *(float2*)(outp + (size_t)(2 * q)     * ODIM) = make_float2(ax0, ay0);
            *(float2*)(outp + (size_t)(2 * q + 1) * ODIM) = make_float2(ax1, ay1);
        }
    }
    // --- reduce denominators across the 16 jj lanes ---
    #pragma unroll
    for (int k = 0; k < 8; k++) {
        #pragma unroll
        for (int m = 1; m < 16; m <<= 1)
            den8[k] += __shfl_xor_sync(0xFFFFFFFFu, den8[k], m);
    }
    if ((tid & 15) == 0) {
        #pragma unroll
        for (int k = 0; k < 8; k++)
            g_pden[((size_t)sp * HEADS + hh) * NN + i0 + rbase + k] = den8[k];
    }
}

// ============================================================
// Kernel 4: reduce splits + softmax div + ELU + residual + LayerNorm
// ============================================================
__global__ __launch_bounds__(256) void k_final(
    const float* __restrict__ gamma, const float* __restrict__ beta,
    float* __restrict__ out)
{
    __shared__ float ysm[32 * 256];
    __shared__ float densm[32 * 4];
    const int tid = threadIdx.x;
    const int i0 = blockIdx.x * 32;
    const int c = tid;
    const int hd = c >> 6;

    if (tid < 128) {
        int hh = tid & 3, r = tid >> 2;
        float d = 0.f;
        #pragma unroll
        for (int s = 0; s < SPLITS; s++)
            d += g_pden[((size_t)s * HEADS + hh) * NN + i0 + r];
        densm[r * 4 + hh] = d;
    }
    __syncthreads();

    #pragma unroll 4
    for (int r = 0; r < 32; r++) {
        float a = 0.f;
        #pragma unroll
        for (int s = 0; s < SPLITS; s++)
            a += g_pacc[((size_t)s * NN + i0 + r) * ODIM + c];
        float v = a / densm[r * 4 + hd];
        v = v > 0.f ? v : (__expf(v) - 1.f);        // ELU
        v += g_resid[(size_t)(i0 + r) * ODIM + c];
        ysm[r * 256 + c] = v;
    }
    __syncthreads();

    const int w = tid >> 5, lane = tid & 31;
    #pragma unroll
    for (int rr = 0; rr < 4; rr++) {
        int r = w * 4 + rr;
        float s = 0.f, sq = 0.f;
        #pragma unroll
        for (int q = 0; q < 8; q++) {
            float v = ysm[r * 256 + lane + q * 32];
            s += v; sq += v * v;
        }
        #pragma unroll
        for (int o = 16; o > 0; o >>= 1) {
            s  += __shfl_xor_sync(0xFFFFFFFFu, s,  o);
            sq += __shfl_xor_sync(0xFFFFFFFFu, sq, o);
        }
        float mu   = s * (1.f / 256.f);
        float var  = sq * (1.f / 256.f) - mu * mu;
        float rstd = rsqrtf(var + 1e-5f);
        #pragma unroll
        for (int q = 0; q < 8; q++) {
            int cc = lane + q * 32;
            float v = ysm[r * 256 + cc];
            out[(size_t)(i0 + r) * ODIM + cc] = (v - mu) * rstd * gamma[cc] + beta[cc];
        }
    }
}

// ============================================================
extern "C" void kernel_launch(void* const* d_in, const int* in_sizes, int n_in,
                              void* d_out, int out_size)
{
    const float* x     = (const float*)d_in[0];
    const int*   adj   = (const int*)  d_in[1];
    const float* W     = (const float*)d_in[2];
    const float* a1    = (const float*)d_in[3];
    const float* a2    = (const float*)d_in[4];
    const float* Wr    = (const float*)d_in[5];
    const float* br    = (const float*)d_in[6];
    const float* gamma = (const float*)d_in[7];
    const float* beta  = (const float*)d_in[8];
    float* out = (float*)d_out;

    k_gemm  <<<dim3(512 / 64, NN / 64), 256>>>(x, W, Wr, br);
    k_scores<<<NN / 32, 256>>>(a1, a2);
    k_gmax  <<<1, 256>>>();
    k_attn  <<<dim3(NN / 32, SPLITS), 256>>>(adj);
    k_final <<<NN / 32, 256>>>(gamma, beta, out);
}

// round 14
// speedup vs baseline: 2.2224x; 1.8987x over previous
#include <cuda_runtime.h>
#include <cuda_pipeline.h>
#include <math.h>
#include <stdint.h>

#define NN 4096
#define INDIM 256
#define ODIM 256
#define HEADS 4
#define KT 32
#define NT (NN/KT)        // 128 tiles
#define JSPLITS 2
#define TPC (NT/JSPLITS)  // 64 tiles per CTA
#define VPITCH 72         // V smem row stride (floats): conflict-free b-frags

__device__ float    g_hcat [NN*ODIM];
__device__ float    g_resid[NN*ODIM];
__device__ float    g_htf  [NN*ODIM];      // tf32-rounded copy of g_hcat
__device__ float    g_scol [HEADS*NN];
__device__ float    g_srow [HEADS*NN];
__device__ float4   g_sB   [HEADS*NN];     // (s_col, exp(s_col), exp(0.2 s_col), 0)
__device__ float    g_gmax [HEADS];
__device__ unsigned g_abitT[NT*NN];        // adj bitmask, [tile][i]
__device__ float    g_pnum [JSPLITS*NN*ODIM];   // partial PV numerators
__device__ float    g_pden [JSPLITS*HEADS*NN];  // partial denominators

__device__ __forceinline__ unsigned tf32r(float x) {
    unsigned u;
    asm("cvt.rna.tf32.f32 %0, %1;" : "=r"(u) : "f"(x));
    return u;
}

// ============================================================
// Kernel 1: fused GEMM  out[4096][512] -> g_hcat | g_resid
// ============================================================
__global__ __launch_bounds__(256) void k_gemm(
    const float* __restrict__ x, const float* __restrict__ W,
    const float* __restrict__ Wr, const float* __restrict__ br)
{
    __shared__ float As[16][68];
    __shared__ float Bs[16][68];
    const int tid = threadIdx.x;
    const int tx = tid & 15, ty = tid >> 4;
    const int m0 = blockIdx.y * 64, n0 = blockIdx.x * 64;
    float acc[4][4];
    #pragma unroll
    for (int i = 0; i < 4; i++)
        #pragma unroll
        for (int j = 0; j < 4; j++) acc[i][j] = 0.f;
    for (int k0 = 0; k0 < INDIM; k0 += 16) {
        #pragma unroll
        for (int q = 0; q < 4; q++) {
            int idx = tid + q * 256;
            As[idx & 15][idx >> 4] = x[(m0 + (idx >> 4)) * INDIM + k0 + (idx & 15)];
        }
        #pragma unroll
        for (int q = 0; q < 4; q++) {
            int idx = tid + q * 256;
            int kk = idx >> 6, c = idx & 63, cg = n0 + c;
            float v;
            if (cg < ODIM) v = W[(cg >> 6) * (INDIM * 64) + (k0 + kk) * 64 + (cg & 63)];
            else           v = Wr[(k0 + kk) * ODIM + (cg - ODIM)];
            Bs[kk][c] = v;
        }
        __syncthreads();
        #pragma unroll
        for (int kk = 0; kk < 16; kk++) {
            float a[4], b[4];
            #pragma unroll
            for (int i = 0; i < 4; i++) a[i] = As[kk][ty * 4 + i];
            #pragma unroll
            for (int j = 0; j < 4; j++) b[j] = Bs[kk][tx * 4 + j];
            #pragma unroll
            for (int i = 0; i < 4; i++)
                #pragma unroll
                for (int j = 0; j < 4; j++) acc[i][j] += a[i] * b[j];
        }
        __syncthreads();
    }
    #pragma unroll
    for (int i = 0; i < 4; i++) {
        int rg = m0 + ty * 4 + i;
        #pragma unroll
        for (int j = 0; j < 4; j++) {
            int cg = n0 + tx * 4 + j;
            if (cg < ODIM) g_hcat[rg * ODIM + cg] = acc[i][j];
            else           g_resid[rg * ODIM + (cg - ODIM)] = acc[i][j] + br[cg - ODIM];
        }
    }
}

// ============================================================
__global__ __launch_bounds__(256) void k_scores(
    const float* __restrict__ a1, const float* __restrict__ a2)
{
    __shared__ float hs[32 * 256];
    const int tid = threadIdx.x;
    const int i0 = blockIdx.x * 32;
    #pragma unroll
    for (int q = 0; q < 32; q++)
        hs[tid + q * 256] = g_hcat[i0 * ODIM + tid + q * 256];
    __syncthreads();
    if (tid < 128) {
        int r = tid >> 2, h = tid & 3, lane = tid & 31;
        float s1 = 0.f, s2 = 0.f;
        #pragma unroll
        for (int k0 = 0; k0 < 64; k0++) {
            int k = (k0 + lane) & 63;
            float hv = hs[r * 256 + h * 64 + k];
            s1 += hv * a1[h * 64 + k];
            s2 += hv * a2[h * 64 + k];
        }
        g_scol[h * NN + i0 + r] = s1;
        g_srow[h * NN + i0 + r] = s2;
        g_sB  [h * NN + i0 + r] = make_float4(s1, __expf(s1), __expf(0.2f * s1), 0.f);
    }
}

// ============================================================
__global__ __launch_bounds__(256) void k_gmax()
{
    __shared__ float red[256];
    const int tid = threadIdx.x, h = tid >> 6, l = tid & 63;
    float m = -1e30f;
    for (int n = l; n < NN; n += 64) m = fmaxf(m, g_scol[h * NN + n]);
    red[tid] = m;
    __syncthreads();
    for (int s = 32; s >= 1; s >>= 1) {
        if (l < s) red[tid] = fmaxf(red[tid], red[tid + s]);
        __syncthreads();
    }
    if (l == 0) g_gmax[h] = red[tid];
}

// ============================================================
// pack adj to bitmasks: g_abitT[tile][i]
__global__ __launch_bounds__(256) void k_pack(const int* __restrict__ adj)
{
    const int w = threadIdx.x >> 5, lane = threadIdx.x & 31;
    const int r = blockIdx.x * 8 + w;
    const int* row = adj + (size_t)r * NN;
    #pragma unroll 4
    for (int q = 0; q < NT; q++) {
        unsigned bits = __ballot_sync(0xFFFFFFFFu, row[q * 32 + lane] > 0);
        if (lane == 0) g_abitT[(size_t)q * NN + r] = bits;
    }
}

// ============================================================
// tf32-round g_hcat -> g_htf
__global__ __launch_bounds__(256) void k_cvt()
{
    const int idx = blockIdx.x * 1024 + threadIdx.x * 4;
    const float4 v = *(const float4*)(g_hcat + idx);
    float4 o;
    o.x = __uint_as_float(tf32r(v.x));
    o.y = __uint_as_float(tf32r(v.y));
    o.z = __uint_as_float(tf32r(v.z));
    o.w = __uint_as_float(tf32r(v.w));
    *(float4*)(g_htf + idx) = o;
}

// ============================================================
// Kernel 3: mma.sync tf32 attention.
// CTA = (128 i-rows, head, j-half). 256 threads = 8 warps x 16 rows.
// A (P) fragments computed in registers (exp-free, adj-bitmask);
// B (V) fragments from cp.async-staged smem (stride 72, conflict-free).
// ============================================================
__global__ __launch_bounds__(256, 2) void k_attn()
{
    __shared__ __align__(16) float    vsm[2][KT * VPITCH]; // 18.4 KB
    __shared__ __align__(16) float4   sbsm[2][KT];         // 1 KB
    __shared__ __align__(16) unsigned absm[2][128];        // 1 KB

    const int tid  = threadIdx.x;
    const int wid  = tid >> 5, lane = tid & 31;
    const int grp  = lane >> 2, tg = lane & 3;
    const int i0   = blockIdx.x * 128;
    const int head = blockIdx.y;
    const int sp   = blockIdx.z;
    const int tb   = sp * TPC;            // first global tile

    // row factors
    const int r_lo = wid * 16 + grp, r_hi = r_lo + 8;
    const float gm = g_gmax[head];
    float si_lo = g_srow[head * NN + i0 + r_lo];
    float si_hi = g_srow[head * NN + i0 + r_hi];
    float m_lo = si_lo + gm; m_lo = m_lo > 0.f ? m_lo : 0.2f * m_lo;
    float m_hi = si_hi + gm; m_hi = m_hi > 0.f ? m_hi : 0.2f * m_hi;
    const float A1lo = __expf(si_lo - m_lo), A2lo = __expf(0.2f * si_lo - m_lo);
    const float A1hi = __expf(si_hi - m_hi), A2hi = __expf(0.2f * si_hi - m_hi);
    float den_lo = 0.f, den_hi = 0.f;

    float acc[8][4];
    #pragma unroll
    for (int n = 0; n < 8; n++)
        #pragma unroll
        for (int e = 0; e < 4; e++) acc[n][e] = 0.f;

    // ---- staging: full 32x64 V tile (2 float4/thread) + sB + adj masks ----
    const int jr = tid >> 3, c8 = tid & 7;
    #define STAGE(T, B)                                                            \
    do {                                                                           \
        const int jg = (T) * KT;                                                   \
        const float* vrow = &g_htf[(size_t)(jg + jr) * ODIM + head * 64];          \
        __pipeline_memcpy_async(&vsm[B][jr * VPITCH + c8 * 4],        vrow + c8 * 4,        16); \
        __pipeline_memcpy_async(&vsm[B][jr * VPITCH + (c8 + 8) * 4],  vrow + (c8 + 8) * 4,  16); \
        if (tid < 32)                                                              \
            __pipeline_memcpy_async(&sbsm[B][tid], &g_sB[head * NN + jg + tid], 16);\
        else if (tid < 64)                                                         \
            __pipeline_memcpy_async(&absm[B][(tid - 32) * 4],                      \
                &g_abitT[(size_t)(T) * NN + i0 + (tid - 32) * 4], 16);             \
        __pipeline_commit();                                                       \
    } while (0)

    STAGE(tb, 0);

    for (int t = 0; t < TPC; t++) {
        const int buf = t & 1;
        __pipeline_wait_prior(0);
        __syncthreads();
        if (t + 1 < TPC) STAGE(tb + t + 1, buf ^ 1);

        const unsigned aw_lo = absm[buf][r_lo];
        const unsigned aw_hi = absm[buf][r_hi];

        #pragma unroll
        for (int ks = 0; ks < 4; ks++) {
            const int j1 = ks * 8 + tg, j2 = j1 + 4;
            float4 s1 = sbsm[buf][j1];
            float4 s2 = sbsm[buf][j2];

            bool p1 = (si_lo + s1.x) > 0.f;
            float a0 = (p1 ? A1lo : A2lo) * (p1 ? s1.y : s1.z);
            a0 = ((aw_lo >> j1) & 1u) ? a0 : 0.f;
            bool p2 = (si_hi + s1.x) > 0.f;
            float a1v = (p2 ? A1hi : A2hi) * (p2 ? s1.y : s1.z);
            a1v = ((aw_hi >> j1) & 1u) ? a1v : 0.f;
            bool p3 = (si_lo + s2.x) > 0.f;
            float a2v = (p3 ? A1lo : A2lo) * (p3 ? s2.y : s2.z);
            a2v = ((aw_lo >> j2) & 1u) ? a2v : 0.f;
            bool p4 = (si_hi + s2.x) > 0.f;
            float a3v = (p4 ? A1hi : A2hi) * (p4 ? s2.y : s2.z);
            a3v = ((aw_hi >> j2) & 1u) ? a3v : 0.f;

            const unsigned ra0 = tf32r(a0),  ra1 = tf32r(a1v);
            const unsigned ra2 = tf32r(a2v), ra3 = tf32r(a3v);

            // denominator from the SAME rounded values fed to the MMA
            den_lo += __uint_as_float(ra0) + __uint_as_float(ra2);
            den_hi += __uint_as_float(ra1) + __uint_as_float(ra3);

            const float* v1 = &vsm[buf][j1 * VPITCH + grp];
            const float* v2 = &vsm[buf][j2 * VPITCH + grp];
            #pragma unroll
            for (int n = 0; n < 8; n++) {
                const unsigned b0 = __float_as_uint(v1[n * 8]);
                const unsigned b1 = __float_as_uint(v2[n * 8]);
                asm volatile(
                    "mma.sync.aligned.m16n8k8.row.col.f32.tf32.tf32.f32 "
                    "{%0,%1,%2,%3}, {%4,%5,%6,%7}, {%8,%9}, {%0,%1,%2,%3};"
                    : "+f"(acc[n][0]), "+f"(acc[n][1]), "+f"(acc[n][2]), "+f"(acc[n][3])
                    : "r"(ra0), "r"(ra1), "r"(ra2), "r"(ra3), "r"(b0), "r"(b1));
            }
        }
    }
    #undef STAGE

    // reduce denominators across the 4 tg lanes of each row-group
    #pragma unroll
    for (int o = 1; o < 4; o <<= 1) {
        den_lo += __shfl_xor_sync(0xFFFFFFFFu, den_lo, o);
        den_hi += __shfl_xor_sync(0xFFFFFFFFu, den_hi, o);
    }
    if (tg == 0) {
        g_pden[((size_t)sp * HEADS + head) * NN + i0 + r_lo] = den_lo;
        g_pden[((size_t)sp * HEADS + head) * NN + i0 + r_hi] = den_hi;
    }

    // write numerator fragments (c0,c1 = contiguous cols)
    {
        float* base = g_pnum + (size_t)sp * NN * ODIM + (size_t)i0 * ODIM + head * 64;
        #pragma unroll
        for (int n = 0; n < 8; n++) {
            int col = n * 8 + tg * 2;
            *(float2*)(base + (size_t)r_lo * ODIM + col) = make_float2(acc[n][0], acc[n][1]);
            *(float2*)(base + (size_t)r_hi * ODIM + col) = make_float2(acc[n][2], acc[n][3]);
        }
    }
}

// ============================================================
// Kernel 4: reduce splits + div + ELU + residual + LayerNorm
// ============================================================
__global__ __launch_bounds__(256) void k_final(
    const float* __restrict__ gamma, const float* __restrict__ beta,
    float* __restrict__ out)
{
    __shared__ float ysm[32 * 256];
    __shared__ float densm[32 * 4];
    const int tid = threadIdx.x, i0 = blockIdx.x * 32, c = tid;
    const int hd = c >> 6;

    if (tid < 128) {
        int hh = tid & 3, r = tid >> 2;
        float d = 0.f;
        #pragma unroll
        for (int s = 0; s < JSPLITS; s++)
            d += g_pden[((size_t)s * HEADS + hh) * NN + i0 + r];
        densm[r * 4 + hh] = d;
    }
    __syncthreads();

    #pragma unroll 4
    for (int r = 0; r < 32; r++) {
        float a = 0.f;
        #pragma unroll
        for (int s = 0; s < JSPLITS; s++)
            a += g_pnum[(size_t)s * NN * ODIM + (size_t)(i0 + r) * ODIM + c];
        float v = a / densm[r * 4 + hd];
        v = v > 0.f ? v : (__expf(v) - 1.f);
        v += g_resid[(size_t)(i0 + r) * ODIM + c];
        ysm[r * 256 + c] = v;
    }
    __syncthreads();

    const int w = tid >> 5, lane = tid & 31;
    #pragma unroll
    for (int rr = 0; rr < 4; rr++) {
        int r = w * 4 + rr;
        float s = 0.f, sq = 0.f;
        #pragma unroll
        for (int q = 0; q < 8; q++) {
            float v = ysm[r * 256 + lane + q * 32];
            s += v; sq += v * v;
        }
        #pragma unroll
        for (int o = 16; o > 0; o >>= 1) {
            s  += __shfl_xor_sync(0xFFFFFFFFu, s,  o);
            sq += __shfl_xor_sync(0xFFFFFFFFu, sq, o);
        }
        float mu = s * (1.f / 256.f);
        float var = sq * (1.f / 256.f) - mu * mu;
        float rstd = rsqrtf(var + 1e-5f);
        #pragma unroll
        for (int q = 0; q < 8; q++) {
            int cc = lane + q * 32;
            float v = ysm[r * 256 + cc];
            out[(size_t)(i0 + r) * ODIM + cc] = (v - mu) * rstd * gamma[cc] + beta[cc];
        }
    }
}

// ============================================================
extern "C" void kernel_launch(void* const* d_in, const int* in_sizes, int n_in,
                              void* d_out, int out_size)
{
    const float* x     = (const float*)d_in[0];
    const int*   adj   = (const int*)  d_in[1];
    const float* W     = (const float*)d_in[2];
    const float* a1    = (const float*)d_in[3];
    const float* a2    = (const float*)d_in[4];
    const float* Wr    = (const float*)d_in[5];
    const float* br    = (const float*)d_in[6];
    const float* gamma = (const float*)d_in[7];
    const float* beta  = (const float*)d_in[8];
    float* out = (float*)d_out;

    k_gemm  <<<dim3(8, 64), 256>>>(x, W, Wr, br);
    k_scores<<<128, 256>>>(a1, a2);
    k_gmax  <<<1, 256>>>();
    k_pack  <<<512, 256>>>(adj);
    k_cvt   <<<NN * ODIM / 1024, 256>>>();
    k_attn  <<<dim3(32, HEADS, JSPLITS), 256>>>();
    k_final <<<128, 256>>>(gamma, beta, out);
}

// round 17
// speedup vs baseline: 2.3183x; 1.0431x over previous
#include <cuda_runtime.h>
#include <cuda_pipeline.h>
#include <math.h>
#include <stdint.h>

#define NN 4096
#define INDIM 256
#define ODIM 256
#define HEADS 4
#define KT 32
#define NT (NN/KT)        // 128 tiles
#define JSPLITS 2
#define TPC (NT/JSPLITS)  // 64 tiles per CTA
#define VPITCH 72         // V smem row stride (floats): conflict-free b-frags

__device__ float    g_hcat [NN*ODIM];
__device__ float    g_resid[NN*ODIM];
__device__ float    g_htf  [NN*ODIM];      // tf32-rounded copy of g_hcat
__device__ float    g_scol [HEADS*NN];
__device__ float    g_srow [HEADS*NN];
__device__ float4   g_sB   [HEADS*NN];     // (s_col, exp(s_col), exp(0.2 s_col), 0)
__device__ float    g_gmax [HEADS];
__device__ unsigned g_abitT[NT*NN];        // adj bitmask, [tile][i]
__device__ float    g_pnum [JSPLITS*NN*ODIM];   // partial PV numerators
__device__ float    g_pden [JSPLITS*HEADS*NN];  // partial denominators

__device__ __forceinline__ unsigned tf32r(float x) {
    unsigned u;
    asm("cvt.rna.tf32.f32 %0, %1;" : "=r"(u) : "f"(x));
    return u;
}

// ============================================================
// Kernel 1: fused GEMM  out[4096][512] -> g_hcat(+g_htf) | g_resid
// ============================================================
__global__ __launch_bounds__(256) void k_gemm(
    const float* __restrict__ x, const float* __restrict__ W,
    const float* __restrict__ Wr, const float* __restrict__ br)
{
    __shared__ float As[16][68];
    __shared__ float Bs[16][68];
    const int tid = threadIdx.x;
    const int tx = tid & 15, ty = tid >> 4;
    const int m0 = blockIdx.y * 64, n0 = blockIdx.x * 64;
    float acc[4][4];
    #pragma unroll
    for (int i = 0; i < 4; i++)
        #pragma unroll
        for (int j = 0; j < 4; j++) acc[i][j] = 0.f;
    for (int k0 = 0; k0 < INDIM; k0 += 16) {
        #pragma unroll
        for (int q = 0; q < 4; q++) {
            int idx = tid + q * 256;
            As[idx & 15][idx >> 4] = x[(m0 + (idx >> 4)) * INDIM + k0 + (idx & 15)];
        }
        #pragma unroll
        for (int q = 0; q < 4; q++) {
            int idx = tid + q * 256;
            int kk = idx >> 6, c = idx & 63, cg = n0 + c;
            float v;
            if (cg < ODIM) v = W[(cg >> 6) * (INDIM * 64) + (k0 + kk) * 64 + (cg & 63)];
            else           v = Wr[(k0 + kk) * ODIM + (cg - ODIM)];
            Bs[kk][c] = v;
        }
        __syncthreads();
        #pragma unroll
        for (int kk = 0; kk < 16; kk++) {
            float a[4], b[4];
            #pragma unroll
            for (int i = 0; i < 4; i++) a[i] = As[kk][ty * 4 + i];
            #pragma unroll
            for (int j = 0; j < 4; j++) b[j] = Bs[kk][tx * 4 + j];
            #pragma unroll
            for (int i = 0; i < 4; i++)
                #pragma unroll
                for (int j = 0; j < 4; j++) acc[i][j] += a[i] * b[j];
        }
        __syncthreads();
    }
    #pragma unroll
    for (int i = 0; i < 4; i++) {
        int rg = m0 + ty * 4 + i;
        #pragma unroll
        for (int j = 0; j < 4; j++) {
            int cg = n0 + tx * 4 + j;
            if (cg < ODIM) {
                g_hcat[rg * ODIM + cg] = acc[i][j];
                g_htf [rg * ODIM + cg] = __uint_as_float(tf32r(acc[i][j]));
            } else {
                g_resid[rg * ODIM + (cg - ODIM)] = acc[i][j] + br[cg - ODIM];
            }
        }
    }
}

// ============================================================
// Kernel 2: s_col / s_row + packed (s, B1, B2); 2 threads per (r,h)
// ============================================================
__global__ __launch_bounds__(256) void k_scores(
    const float* __restrict__ a1, const float* __restrict__ a2)
{
    __shared__ float hs[32 * 256];
    const int tid = threadIdx.x;
    const int i0 = blockIdx.x * 32;
    {
        const float4* src = (const float4*)(g_hcat + (size_t)i0 * ODIM);
        float4* dst = (float4*)hs;
        #pragma unroll
        for (int q = 0; q < 8; q++)
            dst[tid + q * 256] = src[tid + q * 256];
    }
    __syncthreads();
    const int r = tid >> 3, h = (tid >> 1) & 3, half = tid & 1;
    const int lane = tid & 31;
    float s1 = 0.f, s2 = 0.f;
    #pragma unroll
    for (int kk = 0; kk < 32; kk++) {
        int k = half * 32 + ((kk + lane) & 31);
        float hv = hs[r * 256 + h * 64 + k];
        s1 += hv * __ldg(&a1[h * 64 + k]);
        s2 += hv * __ldg(&a2[h * 64 + k]);
    }
    s1 += __shfl_xor_sync(0xFFFFFFFFu, s1, 1);
    s2 += __shfl_xor_sync(0xFFFFFFFFu, s2, 1);
    if (half == 0) {
        g_scol[h * NN + i0 + r] = s1;
        g_srow[h * NN + i0 + r] = s2;
        g_sB  [h * NN + i0 + r] = make_float4(s1, __expf(s1), __expf(0.2f * s1), 0.f);
    }
}

// ============================================================
__global__ __launch_bounds__(256) void k_gmax()
{
    __shared__ float red[256];
    const int tid = threadIdx.x, h = tid >> 6, l = tid & 63;
    float m = -1e30f;
    for (int n = l; n < NN; n += 64) m = fmaxf(m, g_scol[h * NN + n]);
    red[tid] = m;
    __syncthreads();
    for (int s = 32; s >= 1; s >>= 1) {
        if (l < s) red[tid] = fmaxf(red[tid], red[tid + s]);
        __syncthreads();
    }
    if (l == 0) g_gmax[h] = red[tid];
}

// ============================================================
// pack adj to bitmasks: int4 loads + nibble shfl-OR assembly.
// warp = one row; iter covers 128 j (4 tiles).
// ============================================================
__global__ __launch_bounds__(256) void k_pack(const int* __restrict__ adj)
{
    const int w = threadIdx.x >> 5, lane = threadIdx.x & 31;
    const int r = blockIdx.x * 8 + w;
    const int4* row = (const int4*)(adj + (size_t)r * NN);
    #pragma unroll 2
    for (int q4 = 0; q4 < 32; q4++) {
        int4 v = row[q4 * 32 + lane];
        unsigned nib = (v.x > 0 ? 1u : 0u) | (v.y > 0 ? 2u : 0u)
                     | (v.z > 0 ? 4u : 0u) | (v.w > 0 ? 8u : 0u);
        unsigned val = nib << ((lane & 7) * 4);
        #pragma unroll
        for (int o = 1; o < 8; o <<= 1)
            val |= __shfl_xor_sync(0xFFFFFFFFu, val, o);
        if ((lane & 7) == 0)
            g_abitT[(size_t)(q4 * 4 + (lane >> 3)) * NN + r] = val;
    }
}

// ============================================================
// Kernel 3: mma.sync tf32 attention (unchanged from R14 winner).
// ============================================================
__global__ __launch_bounds__(256, 2) void k_attn()
{
    __shared__ __align__(16) float    vsm[2][KT * VPITCH]; // 18.4 KB
    __shared__ __align__(16) float4   sbsm[2][KT];         // 1 KB
    __shared__ __align__(16) unsigned absm[2][128];        // 1 KB

    const int tid  = threadIdx.x;
    const int wid  = tid >> 5, lane = tid & 31;
    const int grp  = lane >> 2, tg = lane & 3;
    const int i0   = blockIdx.x * 128;
    const int head = blockIdx.y;
    const int sp   = blockIdx.z;
    const int tb   = sp * TPC;

    const int r_lo = wid * 16 + grp, r_hi = r_lo + 8;
    const float gm = g_gmax[head];
    float si_lo = g_srow[head * NN + i0 + r_lo];
    float si_hi = g_srow[head * NN + i0 + r_hi];
    float m_lo = si_lo + gm; m_lo = m_lo > 0.f ? m_lo : 0.2f * m_lo;
    float m_hi = si_hi + gm; m_hi = m_hi > 0.f ? m_hi : 0.2f * m_hi;
    const float A1lo = __expf(si_lo - m_lo), A2lo = __expf(0.2f * si_lo - m_lo);
    const float A1hi = __expf(si_hi - m_hi), A2hi = __expf(0.2f * si_hi - m_hi);
    float den_lo = 0.f, den_hi = 0.f;

    float acc[8][4];
    #pragma unroll
    for (int n = 0; n < 8; n++)
        #pragma unroll
        for (int e = 0; e < 4; e++) acc[n][e] = 0.f;

    const int jr = tid >> 3, c8 = tid & 7;
    #define STAGE(T, B)                                                            \
    do {                                                                           \
        const int jg = (T) * KT;                                                   \
        const float* vrow = &g_htf[(size_t)(jg + jr) * ODIM + head * 64];          \
        __pipeline_memcpy_async(&vsm[B][jr * VPITCH + c8 * 4],        vrow + c8 * 4,        16); \
        __pipeline_memcpy_async(&vsm[B][jr * VPITCH + (c8 + 8) * 4],  vrow + (c8 + 8) * 4,  16); \
        if (tid < 32)                                                              \
            __pipeline_memcpy_async(&sbsm[B][tid], &g_sB[head * NN + jg + tid], 16);\
        else if (tid < 64)                                                         \
            __pipeline_memcpy_async(&absm[B][(tid - 32) * 4],                      \
                &g_abitT[(size_t)(T) * NN + i0 + (tid - 32) * 4], 16);             \
        __pipeline_commit();                                                       \
    } while (0)

    STAGE(tb, 0);

    for (int t = 0; t < TPC; t++) {
        const int buf = t & 1;
        __pipeline_wait_prior(0);
        __syncthreads();
        if (t + 1 < TPC) STAGE(tb + t + 1, buf ^ 1);

        const unsigned aw_lo = absm[buf][r_lo];
        const unsigned aw_hi = absm[buf][r_hi];

        #pragma unroll
        for (int ks = 0; ks < 4; ks++) {
            const int j1 = ks * 8 + tg, j2 = j1 + 4;
            float4 s1 = sbsm[buf][j1];
            float4 s2 = sbsm[buf][j2];

            bool p1 = (si_lo + s1.x) > 0.f;
            float a0 = (p1 ? A1lo : A2lo) * (p1 ? s1.y : s1.z);
            a0 = ((aw_lo >> j1) & 1u) ? a0 : 0.f;
            bool p2 = (si_hi + s1.x) > 0.f;
            float a1v = (p2 ? A1hi : A2hi) * (p2 ? s1.y : s1.z);
            a1v = ((aw_hi >> j1) & 1u) ? a1v : 0.f;
            bool p3 = (si_lo + s2.x) > 0.f;
            float a2v = (p3 ? A1lo : A2lo) * (p3 ? s2.y : s2.z);
            a2v = ((aw_lo >> j2) & 1u) ? a2v : 0.f;
            bool p4 = (si_hi + s2.x) > 0.f;
            float a3v = (p4 ? A1hi : A2hi) * (p4 ? s2.y : s2.z);
            a3v = ((aw_hi >> j2) & 1u) ? a3v : 0.f;

            const unsigned ra0 = tf32r(a0),  ra1 = tf32r(a1v);
            const unsigned ra2 = tf32r(a2v), ra3 = tf32r(a3v);

            den_lo += __uint_as_float(ra0) + __uint_as_float(ra2);
            den_hi += __uint_as_float(ra1) + __uint_as_float(ra3);

            const float* v1 = &vsm[buf][j1 * VPITCH + grp];
            const float* v2 = &vsm[buf][j2 * VPITCH + grp];
            #pragma unroll
            for (int n = 0; n < 8; n++) {
                const unsigned b0 = __float_as_uint(v1[n * 8]);
                const unsigned b1 = __float_as_uint(v2[n * 8]);
                asm volatile(
                    "mma.sync.aligned.m16n8k8.row.col.f32.tf32.tf32.f32 "
                    "{%0,%1,%2,%3}, {%4,%5,%6,%7}, {%8,%9}, {%0,%1,%2,%3};"
                    : "+f"(acc[n][0]), "+f"(acc[n][1]), "+f"(acc[n][2]), "+f"(acc[n][3])
                    : "r"(ra0), "r"(ra1), "r"(ra2), "r"(ra3), "r"(b0), "r"(b1));
            }
        }
    }
    #undef STAGE

    #pragma unroll
    for (int o = 1; o < 4; o <<= 1) {
        den_lo += __shfl_xor_sync(0xFFFFFFFFu, den_lo, o);
        den_hi += __shfl_xor_sync(0xFFFFFFFFu, den_hi, o);
    }
    if (tg == 0) {
        g_pden[((size_t)sp * HEADS + head) * NN + i0 + r_lo] = den_lo;
        g_pden[((size_t)sp * HEADS + head) * NN + i0 + r_hi] = den_hi;
    }

    {
        float* base = g_pnum + (size_t)sp * NN * ODIM + (size_t)i0 * ODIM + head * 64;
        #pragma unroll
        for (int n = 0; n < 8; n++) {
            int col = n * 8 + tg * 2;
            *(float2*)(base + (size_t)r_lo * ODIM + col) = make_float2(acc[n][0], acc[n][1]);
            *(float2*)(base + (size_t)r_hi * ODIM + col) = make_float2(acc[n][2], acc[n][3]);
        }
    }
}

// ============================================================
// Kernel 4: reduce splits + div + ELU + residual + LayerNorm
// ============================================================
__global__ __launch_bounds__(256) void k_final(
    const float* __restrict__ gamma, const float* __restrict__ beta,
    float* __restrict__ out)
{
    __shared__ float ysm[32 * 256];
    __shared__ float densm[32 * 4];
    const int tid = threadIdx.x, i0 = blockIdx.x * 32, c = tid;
    const int hd = c >> 6;

    if (tid < 128) {
        int hh = tid & 3, r = tid >> 2;
        float d = 0.f;
        #pragma unroll
        for (int s = 0; s < JSPLITS; s++)
            d += g_pden[((size_t)s * HEADS + hh) * NN + i0 + r];
        densm[r * 4 + hh] = d;
    }
    __syncthreads();

    #pragma unroll 4
    for (int r = 0; r < 32; r++) {
        float a = 0.f;
        #pragma unroll
        for (int s = 0; s < JSPLITS; s++)
            a += g_pnum[(size_t)s * NN * ODIM + (size_t)(i0 + r) * ODIM + c];
        float v = a / densm[r * 4 + hd];
        v = v > 0.f ? v : (__expf(v) - 1.f);
        v += g_resid[(size_t)(i0 + r) * ODIM + c];
        ysm[r * 256 + c] = v;
    }
    __syncthreads();

    const int w = tid >> 5, lane = tid & 31;
    #pragma unroll
    for (int rr = 0; rr < 4; rr++) {
        int r = w * 4 + rr;
        float s = 0.f, sq = 0.f;
        #pragma unroll
        for (int q = 0; q < 8; q++) {
            float v = ysm[r * 256 + lane + q * 32];
            s += v; sq += v * v;
        }
        #pragma unroll
        for (int o = 16; o > 0; o >>= 1) {
            s  += __shfl_xor_sync(0xFFFFFFFFu, s,  o);
            sq += __shfl_xor_sync(0xFFFFFFFFu, sq, o);
        }
        float mu = s * (1.f / 256.f);
        float var = sq * (1.f / 256.f) - mu * mu;
        float rstd = rsqrtf(var + 1e-5f);
        #pragma unroll
        for (int q = 0; q < 8; q++) {
            int cc = lane + q * 32;
            float v = ysm[r * 256 + cc];
            out[(size_t)(i0 + r) * ODIM + cc] = (v - mu) * rstd * gamma[cc] + beta[cc];
        }
    }
}

// ============================================================
extern "C" void kernel_launch(void* const* d_in, const int* in_sizes, int n_in,
                              void* d_out, int out_size)
{
    const float* x     = (const float*)d_in[0];
    const int*   adj   = (const int*)  d_in[1];
    const float* W     = (const float*)d_in[2];
    const float* a1    = (const float*)d_in[3];
    const float* a2    = (const float*)d_in[4];
    const float* Wr    = (const float*)d_in[5];
    const float* br    = (const float*)d_in[6];
    const float* gamma = (const float*)d_in[7];
    const float* beta  = (const float*)d_in[8];
    float* out = (float*)d_out;

    k_gemm  <<<dim3(8, 64), 256>>>(x, W, Wr, br);
    k_scores<<<128, 256>>>(a1, a2);
    k_gmax  <<<1, 256>>>();
    k_pack  <<<512, 256>>>(adj);
    k_attn  <<<dim3(32, HEADS, JSPLITS), 256>>>();
    k_final <<<128, 256>>>(gamma, beta, out);
}